// round 1
// baseline (speedup 1.0000x reference)
#include <cuda_runtime.h>
#include <math.h>

#define NPATH 11
#define MULC 128
#define XDIM 1152
#define YDIM 9
#define WPER 180224
#define NSAMP 1024
#define CGTOT 363
#define ZTOT 4480
#define REDSTRIDE 37
#define REDQ (32 * REDSTRIDE)      // 1184
#define ZBUF (4 * REDQ)            // 4736 >= ZTOT

// path tables
__constant__ int cL1[NPATH]  = {0,0,0,1,1,1,1,2,2,2,2};
__constant__ int cL2[NPATH]  = {0,1,2,0,1,1,2,0,1,2,2};
__constant__ int cL3[NPATH]  = {0,1,2,1,0,2,1,2,1,0,2};
__constant__ int cCGO[NPATH] = {0,1,10,35,44,53,98,143,168,213,238};
__constant__ int cXOFF[NPATH]= {0,0,0,128,128,128,128,512,512,512,512};
__constant__ int cYOFF[NPATH]= {0,1,4,0,1,1,4,0,1,4,4};
__constant__ int cZOFF[NPATH]= {0,128,512,1152,1536,1664,2304,2688,3328,3712,3840};
__constant__ float cFAN[NPATH]= {384.f,512.f,512.f,512.f,384.f,512.f,512.f,512.f,512.f,384.f,512.f};

__device__ float g_cg[CGTOT];

// ---------------- CG init (exact per-reference computation) ----------------

__device__ __forceinline__ double dF(int n) {
    const double T[8] = {1.0,1.0,2.0,6.0,24.0,120.0,720.0,5040.0};
    return T[n];
}

__device__ double su2cg(int j1,int m1,int j2,int m2,int j3,int m3) {
    if (m1 + m2 != m3) return 0.0;
    int vmin = -j1 + j2 + m3; if (-j1 + m1 > vmin) vmin = -j1 + m1; if (vmin < 0) vmin = 0;
    int vmax = j2 + j3 + m1; if (j3 - j1 + j2 < vmax) vmax = j3 - j1 + j2; if (j3 + m3 < vmax) vmax = j3 + m3;
    double c = sqrt((2.0*j3+1.0)*dF(j3+j1-j2)*dF(j3-j1+j2)*dF(j1+j2-j3)*dF(j3+m3)*dF(j3-m3)
                    /(dF(j1+j2+j3+1)*dF(j1-m1)*dF(j1+m1)*dF(j2-m2)*dF(j2+m2)));
    double s = 0.0;
    for (int v = vmin; v <= vmax; v++) {
        double term = dF(j2+j3+m1-v)*dF(j1-m1+v)
                      /(dF(v)*dF(j3-j1+j2-v)*dF(j3+m3-v)*dF(v+j1-j2-m3));
        s += ((v + j2 + m2) & 1) ? -term : term;
    }
    return c * s;
}

// Q: change of basis real <- complex spherical harmonics (e3nn), times (-i)^l
__device__ void buildQ(int l, double* qr, double* qi) {
    int d = 2*l + 1;
    for (int e = 0; e < d*d; e++) { qr[e] = 0.0; qi[e] = 0.0; }
    const double is2 = 0.70710678118654752440;
    for (int m = -l; m < 0; m++) {
        int r = l + m;
        qr[r*d + (l - m)] = is2;       // 1/sqrt2 at col l+|m|
        qi[r*d + (l + m)] = -is2;      // -i/sqrt2 at col l-|m|
    }
    qr[l*d + l] = 1.0;
    for (int m = 1; m <= l; m++) {
        int r = l + m;
        double sgn = (m & 1) ? -1.0 : 1.0;
        qr[r*d + (l + m)] = sgn * is2;   // (-1)^m/sqrt2
        qi[r*d + (l - m)] = sgn * is2;   // i(-1)^m/sqrt2
    }
    if (l == 1) {          // multiply by -i : (re,im) -> (im,-re)
        for (int e = 0; e < d*d; e++) { double a = qr[e], b = qi[e]; qr[e] = b; qi[e] = -a; }
    } else if (l == 2) {   // multiply by -1
        for (int e = 0; e < d*d; e++) { qr[e] = -qr[e]; qi[e] = -qi[e]; }
    }
}

__global__ void cg_init_kernel() {
    __shared__ double Csh[125];
    __shared__ float  Crsh[125];
    __shared__ double Q1r[25], Q1i[25], Q2r[25], Q2i[25], Q3r[25], Q3i[25];
    __shared__ float  red[128];
    int p = blockIdx.x, t = threadIdx.x;
    int l1 = cL1[p], l2 = cL2[p], l3 = cL3[p];
    int d1 = 2*l1+1, d2 = 2*l2+1, d3 = 2*l3+1;
    int nC = d1*d2*d3;
    if (t == 0) { buildQ(l1, Q1r, Q1i); buildQ(l2, Q2r, Q2i); buildQ(l3, Q3r, Q3i); }
    for (int e = t; e < nC; e += blockDim.x) {
        int i = e / (d2*d3), j = (e / d3) % d2, nn = e % d3;
        Csh[e] = su2cg(l1, i - l1, l2, j - l2, l3, nn - l3);
    }
    __syncthreads();
    // Cr[j,l,m] = Re( sum_{i,k,n} Q1[i,j] Q2[k,l] conj(Q3[n,m]) C[i,k,n] )
    float psum = 0.f;
    for (int e = t; e < nC; e += blockDim.x) {
        int jj = e / (d2*d3), ll = (e / d3) % d2, mm = e % d3;
        double sr = 0.0;
        for (int i = 0; i < d1; i++) {
            double q1r = Q1r[i*d1 + jj], q1i = Q1i[i*d1 + jj];
            for (int k = 0; k < d2; k++) {
                double q2r = Q2r[k*d2 + ll], q2i = Q2i[k*d2 + ll];
                double ar = q1r*q2r - q1i*q2i;
                double ai = q1r*q2i + q1i*q2r;
                for (int nn = 0; nn < d3; nn++) {
                    double c = Csh[(i*d2 + k)*d3 + nn];
                    if (c != 0.0)
                        sr += c * (ar * Q3r[nn*d3 + mm] + ai * Q3i[nn*d3 + mm]);
                }
            }
        }
        Crsh[e] = (float)sr;
        psum += (float)(sr * sr);
    }
    red[t] = psum;
    __syncthreads();
    for (int s = 64; s > 0; s >>= 1) { if (t < s) red[t] += red[t + s]; __syncthreads(); }
    float scale = sqrtf((float)(2*l3 + 1)) / (sqrtf(red[0]) * sqrtf(cFAN[p]));
    for (int e = t; e < nC; e += blockDim.x) g_cg[cCGO[p] + e] = Crsh[e] * scale;
}

// ---------------- Main TP kernel: 1 CTA/sample, 128 threads ----------------

template<int K3, int B>
__device__ __forceinline__ void accum_path(const float* __restrict__ wp,
                                           const float* __restrict__ zp,
                                           float* __restrict__ acc,
                                           int lane4, int q) {
    const float* wq = wp + q * 32 * 128 + lane4;
    const float* zq = zp + q * 32 * K3;
    #pragma unroll 4
    for (int ui = 0; ui < 32; ui++) {
        float4 wv = __ldg(reinterpret_cast<const float4*>(wq + ui * 128));
        #pragma unroll
        for (int k = 0; k < K3; k++) {
            float zv = zq[ui * K3 + k];
            acc[ 0 + B + k] += wv.x * zv;
            acc[ 9 + B + k] += wv.y * zv;
            acc[18 + B + k] += wv.z * zv;
            acc[27 + B + k] += wv.w * zv;
        }
    }
}

__global__ void tp_kernel(const float* __restrict__ x,
                          const float* __restrict__ y,
                          const float* __restrict__ w,
                          float* __restrict__ out) {
    __shared__ float xsh[XDIM];
    __shared__ float ysh[16];
    __shared__ float cgsh[CGTOT];
    __shared__ float zsh[ZBUF];

    const int n = blockIdx.x;
    const int t = threadIdx.x;

    const float* xn = x + (size_t)n * XDIM;
    for (int i = t; i < XDIM; i += 128) xsh[i] = xn[i];
    if (t < YDIM) ysh[t] = y[(size_t)n * YDIM + t];
    for (int i = t; i < CGTOT; i += 128) cgsh[i] = g_cg[i];
    __syncthreads();

    // Phase 1: z[p][u][k] = sum_{i,j} CGeff[i,j,k] * x_{i1}[u,i] * y_{i2}[j]
    {
        const int u = t;
        for (int p = 0; p < NPATH; p++) {
            int d1 = 2*cL1[p] + 1, d2 = 2*cL2[p] + 1, d3 = 2*cL3[p] + 1;
            const float* cg = cgsh + cCGO[p];
            const float* xb = xsh + cXOFF[p] + u * d1;
            const float* yb = ysh + cYOFF[p];
            float zv[5] = {0.f, 0.f, 0.f, 0.f, 0.f};
            for (int i = 0; i < d1; i++) {
                float xv = xb[i];
                for (int j = 0; j < d2; j++) {
                    float xy = xv * yb[j];
                    const float* cgr = cg + (i * d2 + j) * d3;
                    for (int k = 0; k < d3; k++) zv[k] += cgr[k] * xy;
                }
            }
            for (int k = 0; k < d3; k++) zsh[cZOFF[p] + u * d3 + k] = zv[k];
        }
    }
    __syncthreads();

    // Phase 2: stream the 704KB of per-sample weights.
    // warp q handles u in [q*32, q*32+32); lane handles w in [4*lane, 4*lane+4)
    const int lane = t & 31, q = t >> 5;
    const int lane4 = lane * 4;
    const float* wn = w + (size_t)n * WPER;

    float acc[36];
    #pragma unroll
    for (int s = 0; s < 36; s++) acc[s] = 0.f;

    accum_path<1, 0>(wn + 0  * 16384, zsh + 0,    acc, lane4, q);
    accum_path<3, 1>(wn + 1  * 16384, zsh + 128,  acc, lane4, q);
    accum_path<5, 4>(wn + 2  * 16384, zsh + 512,  acc, lane4, q);
    accum_path<3, 1>(wn + 3  * 16384, zsh + 1152, acc, lane4, q);
    accum_path<1, 0>(wn + 4  * 16384, zsh + 1536, acc, lane4, q);
    accum_path<5, 4>(wn + 5  * 16384, zsh + 1664, acc, lane4, q);
    accum_path<3, 1>(wn + 6  * 16384, zsh + 2304, acc, lane4, q);
    accum_path<5, 4>(wn + 7  * 16384, zsh + 2688, acc, lane4, q);
    accum_path<3, 1>(wn + 8  * 16384, zsh + 3328, acc, lane4, q);
    accum_path<1, 0>(wn + 9  * 16384, zsh + 3712, acc, lane4, q);
    accum_path<5, 4>(wn + 10 * 16384, zsh + 3840, acc, lane4, q);

    // Phase 3: reduce 4 u-partials per (w,slot); reuse zsh (padded stride 37)
    __syncthreads();
    float* red = zsh;
    #pragma unroll
    for (int s = 0; s < 36; s++) red[q * REDQ + lane * REDSTRIDE + s] = acc[s];
    __syncthreads();

    // thread (lane, q) finalizes all 9 outputs of w = 4*lane + q
    float* outn = out + (size_t)n * XDIM;
    const int wdx = lane * 4 + q;
    #pragma unroll
    for (int s9 = 0; s9 < 9; s9++) {
        int s = q * 9 + s9;
        float v = red[0 * REDQ + lane * REDSTRIDE + s]
                + red[1 * REDQ + lane * REDSTRIDE + s]
                + red[2 * REDQ + lane * REDSTRIDE + s]
                + red[3 * REDQ + lane * REDSTRIDE + s];
        int o = (s9 == 0) ? wdx
              : (s9 < 4)  ? 128 + wdx * 3 + (s9 - 1)
                          : 512 + wdx * 5 + (s9 - 4);
        outn[o] = v;
    }
}

extern "C" void kernel_launch(void* const* d_in, const int* in_sizes, int n_in,
                              void* d_out, int out_size) {
    const float* x = nullptr;
    const float* y = nullptr;
    const float* w = nullptr;
    for (int i = 0; i < n_in; i++) {
        long sz = in_sizes[i];
        if      (sz == (long)NSAMP * XDIM) x = (const float*)d_in[i];
        else if (sz == (long)NSAMP * YDIM) y = (const float*)d_in[i];
        else if (sz == (long)NSAMP * WPER) w = (const float*)d_in[i];
    }
    if (!x) x = (const float*)d_in[0];
    if (!y) y = (const float*)d_in[1];
    if (!w) w = (const float*)d_in[2];

    cg_init_kernel<<<NPATH, 128>>>();
    tp_kernel<<<NSAMP, 128>>>(x, y, w, (float*)d_out);
}

// round 4
// speedup vs baseline: 1.6460x; 1.6460x over previous
#include <cuda_runtime.h>
#include <math.h>

#define NPATH 11
#define MULC 128
#define XDIM 1152
#define YDIM 9
#define WPER 180224
#define NSAMP 1024
#define CGTOT 363

// path tables (for cg_init)
__constant__ int cL1[NPATH]  = {0,0,0,1,1,1,1,2,2,2,2};
__constant__ int cL2[NPATH]  = {0,1,2,0,1,1,2,0,1,2,2};
__constant__ int cL3[NPATH]  = {0,1,2,1,0,2,1,2,1,0,2};
__constant__ int cCGO[NPATH] = {0,1,10,35,44,53,98,143,168,213,238};
__constant__ float cFAN[NPATH]= {384.f,512.f,512.f,512.f,384.f,512.f,512.f,512.f,512.f,384.f,512.f};

__device__ float g_cg[CGTOT];

// ---------------- CG init (exact per-reference computation) ----------------

__device__ __forceinline__ double dF(int n) {
    const double T[8] = {1.0,1.0,2.0,6.0,24.0,120.0,720.0,5040.0};
    return T[n];
}

__device__ double su2cg(int j1,int m1,int j2,int m2,int j3,int m3) {
    if (m1 + m2 != m3) return 0.0;
    int vmin = -j1 + j2 + m3; if (-j1 + m1 > vmin) vmin = -j1 + m1; if (vmin < 0) vmin = 0;
    int vmax = j2 + j3 + m1; if (j3 - j1 + j2 < vmax) vmax = j3 - j1 + j2; if (j3 + m3 < vmax) vmax = j3 + m3;
    double c = sqrt((2.0*j3+1.0)*dF(j3+j1-j2)*dF(j3-j1+j2)*dF(j1+j2-j3)*dF(j3+m3)*dF(j3-m3)
                    /(dF(j1+j2+j3+1)*dF(j1-m1)*dF(j1+m1)*dF(j2-m2)*dF(j2+m2)));
    double s = 0.0;
    for (int v = vmin; v <= vmax; v++) {
        double term = dF(j2+j3+m1-v)*dF(j1-m1+v)
                      /(dF(v)*dF(j3-j1+j2-v)*dF(j3+m3-v)*dF(v+j1-j2-m3));
        s += ((v + j2 + m2) & 1) ? -term : term;
    }
    return c * s;
}

__device__ void buildQ(int l, double* qr, double* qi) {
    int d = 2*l + 1;
    for (int e = 0; e < d*d; e++) { qr[e] = 0.0; qi[e] = 0.0; }
    const double is2 = 0.70710678118654752440;
    for (int m = -l; m < 0; m++) {
        int r = l + m;
        qr[r*d + (l - m)] = is2;
        qi[r*d + (l + m)] = -is2;
    }
    qr[l*d + l] = 1.0;
    for (int m = 1; m <= l; m++) {
        int r = l + m;
        double sgn = (m & 1) ? -1.0 : 1.0;
        qr[r*d + (l + m)] = sgn * is2;
        qi[r*d + (l - m)] = sgn * is2;
    }
    if (l == 1) {
        for (int e = 0; e < d*d; e++) { double a = qr[e], b = qi[e]; qr[e] = b; qi[e] = -a; }
    } else if (l == 2) {
        for (int e = 0; e < d*d; e++) { qr[e] = -qr[e]; qi[e] = -qi[e]; }
    }
}

__global__ void cg_init_kernel() {
    __shared__ double Csh[125];
    __shared__ float  Crsh[125];
    __shared__ double Q1r[25], Q1i[25], Q2r[25], Q2i[25], Q3r[25], Q3i[25];
    __shared__ float  red[128];
    int p = blockIdx.x, t = threadIdx.x;
    int l1 = cL1[p], l2 = cL2[p], l3 = cL3[p];
    int d1 = 2*l1+1, d2 = 2*l2+1, d3 = 2*l3+1;
    int nC = d1*d2*d3;
    if (t == 0) { buildQ(l1, Q1r, Q1i); buildQ(l2, Q2r, Q2i); buildQ(l3, Q3r, Q3i); }
    for (int e = t; e < nC; e += blockDim.x) {
        int i = e / (d2*d3), j = (e / d3) % d2, nn = e % d3;
        Csh[e] = su2cg(l1, i - l1, l2, j - l2, l3, nn - l3);
    }
    __syncthreads();
    float psum = 0.f;
    for (int e = t; e < nC; e += blockDim.x) {
        int jj = e / (d2*d3), ll = (e / d3) % d2, mm = e % d3;
        double sr = 0.0;
        for (int i = 0; i < d1; i++) {
            double q1r = Q1r[i*d1 + jj], q1i = Q1i[i*d1 + jj];
            for (int k = 0; k < d2; k++) {
                double q2r = Q2r[k*d2 + ll], q2i = Q2i[k*d2 + ll];
                double ar = q1r*q2r - q1i*q2i;
                double ai = q1r*q2i + q1i*q2r;
                for (int nn = 0; nn < d3; nn++) {
                    double c = Csh[(i*d2 + k)*d3 + nn];
                    if (c != 0.0)
                        sr += c * (ar * Q3r[nn*d3 + mm] + ai * Q3i[nn*d3 + mm]);
                }
            }
        }
        Crsh[e] = (float)sr;
        psum += (float)(sr * sr);
    }
    red[t] = psum;
    __syncthreads();
    for (int s = 64; s > 0; s >>= 1) { if (t < s) red[t] += red[t + s]; __syncthreads(); }
    float scale = sqrtf((float)(2*l3 + 1)) / (sqrtf(red[0]) * sqrtf(cFAN[p]));
    for (int e = t; e < nC; e += blockDim.x) g_cg[cCGO[p] + e] = Crsh[e] * scale;
}

// ---------------- Main TP kernel: 3 CTAs/sample (by output irrep) ----------
// Group tables as __host__ __device__ constexpr FUNCTIONS (member arrays
// trigger device ODR issues; plain constexpr defaults to __host__-only).

#define HDC static __host__ __device__ constexpr int

template<int G> struct GInfo;
template<> struct GInfo<0> {   // out l=0 (k=1): paths 0,4,9
    static constexpr int NP = 3, K3 = 1, OB = 0;
    HDC PID(int i) { return i==0 ? 0 : i==1 ? 4 : 9; }
    HDC D1 (int i) { return i==0 ? 1 : i==1 ? 3 : 5; }
    HDC D2 (int i) { return i==0 ? 1 : i==1 ? 3 : 5; }
    HDC XO (int i) { return i==0 ? 0 : i==1 ? 128 : 512; }
    HDC YO (int i) { return i==0 ? 0 : i==1 ? 1 : 4; }
    HDC CGO(int i) { return i==0 ? 0 : i==1 ? 44 : 213; }
};
template<> struct GInfo<1> {   // out l=1 (k=3): paths 1,3,6,8
    static constexpr int NP = 4, K3 = 3, OB = 128;
    HDC PID(int i) { return i==0 ? 1 : i==1 ? 3 : i==2 ? 6 : 8; }
    HDC D1 (int i) { return i==0 ? 1 : i==1 ? 3 : i==2 ? 3 : 5; }
    HDC D2 (int i) { return i==0 ? 3 : i==1 ? 1 : i==2 ? 5 : 3; }
    HDC XO (int i) { return i==0 ? 0 : i==1 ? 128 : i==2 ? 128 : 512; }
    HDC YO (int i) { return i==0 ? 1 : i==1 ? 0 : i==2 ? 4 : 1; }
    HDC CGO(int i) { return i==0 ? 1 : i==1 ? 35 : i==2 ? 98 : 168; }
};
template<> struct GInfo<2> {   // out l=2 (k=5): paths 2,5,7,10
    static constexpr int NP = 4, K3 = 5, OB = 512;
    HDC PID(int i) { return i==0 ? 2 : i==1 ? 5 : i==2 ? 7 : 10; }
    HDC D1 (int i) { return i==0 ? 1 : i==1 ? 3 : i==2 ? 5 : 5; }
    HDC D2 (int i) { return i==0 ? 5 : i==1 ? 3 : i==2 ? 1 : 5; }
    HDC XO (int i) { return i==0 ? 0 : i==1 ? 128 : i==2 ? 512 : 512; }
    HDC YO (int i) { return i==0 ? 4 : i==1 ? 1 : i==2 ? 0 : 4; }
    HDC CGO(int i) { return i==0 ? 10 : i==1 ? 53 : i==2 ? 143 : 238; }
};

#define ZBUF 5120   // max(NP*128*K3*2, 8*128*K3) over groups = 5120 floats

// Phase-1 body: z[p][u][k] for one path, stored duplicated for LDS.64.
template<class GI>
__device__ __forceinline__ void phase1_path(GI, int pl,
                                            const float* __restrict__ x,
                                            const float* __restrict__ ysh,
                                            float* zsh, int n, int u) {
    constexpr int K3 = GI::K3;
    float zv[K3];
    #pragma unroll
    for (int k = 0; k < K3; k++) zv[k] = 0.f;
    const int d1 = GI::D1(pl), d2 = GI::D2(pl);
    const float* xb = x + (size_t)n * XDIM + GI::XO(pl) + u * d1;
    for (int i = 0; i < d1; i++) {
        float xv = xb[i];
        for (int j = 0; j < d2; j++) {
            float xy = xv * ysh[GI::YO(pl) + j];
            const float* cgr = g_cg + GI::CGO(pl) + (i * d2 + j) * K3;
            #pragma unroll
            for (int k = 0; k < K3; k++) zv[k] += __ldg(cgr + k) * xy;
        }
    }
    int base = (pl * 128 + u) * K3 * 2;
    #pragma unroll
    for (int k = 0; k < K3; k++) {
        zsh[base + 2*k]     = zv[k];
        zsh[base + 2*k + 1] = zv[k];
    }
}

template<int G>
__device__ __forceinline__ void run_group(const float* __restrict__ x,
                                          const float* __restrict__ ysh,
                                          const float* __restrict__ w,
                                          float* __restrict__ out,
                                          float* zsh, int n, int t) {
    using GI = GInfo<G>;
    constexpr int NP = GI::NP, K3 = GI::K3;

    // ---- Phase 1 ----
    if (t < 128) {
        const int u = t;
        #pragma unroll
        for (int pl = 0; pl < NP; pl++)
            phase1_path(GI{}, pl, x, ysh, zsh, n, u);
    }
    __syncthreads();

    // ---- Phase 2: stream weights. warp q owns u in [16q,16q+16),
    //      lane owns w = 4*lane..4*lane+3 (LDG.128), f32x2 FMA ----
    const int lane = t & 31, q = t >> 5;
    const float* wn = w + (size_t)n * WPER;
    const float* wq[NP];
    const float* zq[NP];
    #pragma unroll
    for (int p = 0; p < NP; p++) {
        wq[p] = wn + GI::PID(p) * 16384 + (q * 16) * 128 + lane * 4;
        zq[p] = zsh + (p * 128 + q * 16) * K3 * 2;
    }

    unsigned long long acc0[K3], acc1[K3];
    #pragma unroll
    for (int k = 0; k < K3; k++) { acc0[k] = 0ull; acc1[k] = 0ull; }

    #pragma unroll 2
    for (int ui = 0; ui < 16; ui++) {
        #pragma unroll
        for (int p = 0; p < NP; p++) {
            ulonglong2 wv = __ldg(reinterpret_cast<const ulonglong2*>(wq[p] + ui * 128));
            #pragma unroll
            for (int k = 0; k < K3; k++) {
                unsigned long long zz =
                    *reinterpret_cast<const unsigned long long*>(zq[p] + (ui * K3 + k) * 2);
                asm("fma.rn.f32x2 %0, %1, %2, %0;" : "+l"(acc0[k]) : "l"(wv.x), "l"(zz));
                asm("fma.rn.f32x2 %0, %1, %2, %0;" : "+l"(acc1[k]) : "l"(wv.y), "l"(zz));
            }
        }
    }

    // ---- Phase 3: cross-warp reduction (reuse zsh) ----
    __syncthreads();
    float* red = zsh;
    #pragma unroll
    for (int k = 0; k < K3; k++) {
        float lo, hi;
        asm("mov.b64 {%0,%1}, %2;" : "=f"(lo), "=f"(hi) : "l"(acc0[k]));
        red[(q * 128 + lane * 4 + 0) * K3 + k] = lo;
        red[(q * 128 + lane * 4 + 1) * K3 + k] = hi;
        asm("mov.b64 {%0,%1}, %2;" : "=f"(lo), "=f"(hi) : "l"(acc1[k]));
        red[(q * 128 + lane * 4 + 2) * K3 + k] = lo;
        red[(q * 128 + lane * 4 + 3) * K3 + k] = hi;
    }
    __syncthreads();

    if (t < 128) {
        const int wi = t;
        float* outn = out + (size_t)n * XDIM + GI::OB + wi * K3;
        #pragma unroll
        for (int k = 0; k < K3; k++) {
            float v = 0.f;
            #pragma unroll
            for (int qq = 0; qq < 8; qq++) v += red[(qq * 128 + wi) * K3 + k];
            outn[k] = v;
        }
    }
}

__global__ void __launch_bounds__(256, 4)
tp_kernel(const float* __restrict__ x,
          const float* __restrict__ y,
          const float* __restrict__ w,
          float* __restrict__ out) {
    __shared__ float zsh[ZBUF];
    __shared__ float ysh[12];
    const int n = blockIdx.x, g = blockIdx.y, t = threadIdx.x;
    if (t < YDIM) ysh[t] = y[(size_t)n * YDIM + t];
    __syncthreads();
    if (g == 0)      run_group<0>(x, ysh, w, out, zsh, n, t);
    else if (g == 1) run_group<1>(x, ysh, w, out, zsh, n, t);
    else             run_group<2>(x, ysh, w, out, zsh, n, t);
}

extern "C" void kernel_launch(void* const* d_in, const int* in_sizes, int n_in,
                              void* d_out, int out_size) {
    const float* x = nullptr;
    const float* y = nullptr;
    const float* w = nullptr;
    for (int i = 0; i < n_in; i++) {
        long sz = in_sizes[i];
        if      (sz == (long)NSAMP * XDIM) x = (const float*)d_in[i];
        else if (sz == (long)NSAMP * YDIM) y = (const float*)d_in[i];
        else if (sz == (long)NSAMP * WPER) w = (const float*)d_in[i];
    }
    if (!x) x = (const float*)d_in[0];
    if (!y) y = (const float*)d_in[1];
    if (!w) w = (const float*)d_in[2];

    cg_init_kernel<<<NPATH, 128>>>();
    tp_kernel<<<dim3(NSAMP, 3), 256>>>(x, y, w, (float*)d_out);
}